// round 11
// baseline (speedup 1.0000x reference)
#include <cuda_runtime.h>
#include <cuda_bf16.h>
#include <math.h>
#include <stdint.h>

// Problem constants
#define D   512
#define QN  16
#define NT  4096   // B*L tokens
#define NG  512    // N gathered groups
#define PP  64     // group size P

#define SCALE 0.04419417382415922f  // 1/sqrt(512)

// Scratch (allocation-free: __device__ globals)
__device__ float g_Vp[NT * D];            // patch @ Wv + bv      [4096,512]
__device__ __nv_bfloat16 g_Ahi[NT * D];   // bf16 hi split of patch
__device__ __nv_bfloat16 g_Alo[NT * D];   // bf16 lo split of patch
__device__ __nv_bfloat16 g_Bhi[D * D];    // bf16 hi split of Wv^T ([n][k])
__device__ __nv_bfloat16 g_Blo[D * D];    // bf16 lo split of Wv^T
__device__ float g_sp[NT * QN];           // scaled patch scores  [4096,16]
__device__ float g_VQ[QN * D];            // Q0 @ Wv + bv         [16,512]
__device__ float g_Ak[QN * D];            // (Wk @ Q0^T)^T        [16,512]
__device__ float g_pfp[8][NT];            // partial Vp @ Wf per n-tile
__device__ float g_tq[QN];                // VQ @ Wf              [16]
__device__ float g_sself[QN];             // self-token scores    [16]
__device__ float g_qbk[QN];               // Q0[q] . bk           [16]

// ---- PTX helpers (all sm_80-level, valid for compute_103 target) -----------
__device__ __forceinline__ uint32_t smem_u32(const void* p) {
    uint32_t a;
    asm("{ .reg .u64 tmp; cvta.to.shared.u64 tmp, %1; cvt.u32.u64 %0, tmp; }"
        : "=r"(a) : "l"(p));
    return a;
}
__device__ __forceinline__ void cp16(uint32_t sdst, const void* gsrc) {
    asm volatile("cp.async.cg.shared.global [%0], [%1], 16;"
                 :: "r"(sdst), "l"(gsrc) : "memory");
}
#define CP_COMMIT() asm volatile("cp.async.commit_group;" ::: "memory")
#define CP_WAIT(n)  asm volatile("cp.async.wait_group %0;" :: "n"(n) : "memory")

__device__ __forceinline__ void ldm_x4(uint32_t* r, uint32_t addr) {
    asm volatile("ldmatrix.sync.aligned.m8n8.x4.shared.b16 {%0,%1,%2,%3}, [%4];"
                 : "=r"(r[0]), "=r"(r[1]), "=r"(r[2]), "=r"(r[3]) : "r"(addr));
}
__device__ __forceinline__ void mma16816(float* c, const uint32_t* a, const uint32_t* b) {
    asm volatile("mma.sync.aligned.m16n8k16.row.col.f32.bf16.bf16.f32 "
                 "{%0,%1,%2,%3}, {%4,%5,%6,%7}, {%8,%9}, {%0,%1,%2,%3};"
                 : "+f"(c[0]), "+f"(c[1]), "+f"(c[2]), "+f"(c[3])
                 : "r"(a[0]), "r"(a[1]), "r"(a[2]), "r"(a[3]), "r"(b[0]), "r"(b[1]));
}

// ---------------------------------------------------------------------------
// k_pre: grid (16, 2), block 512. Fused projections + scalar reductions.
// ---------------------------------------------------------------------------
__global__ void k_pre(const float* __restrict__ query, const float* __restrict__ Wk,
                      const float* __restrict__ Wv, const float* __restrict__ bv,
                      const float* __restrict__ bk, const float* __restrict__ Wf) {
    __shared__ float q0[D];
    __shared__ float red[2][16];
    int q = blockIdx.x, t = threadIdx.x;
    int w = t >> 5, lane = t & 31;
    q0[t] = query[q * D + t];
    __syncthreads();

    float r0v = 0.f, r1v = 0.f;
    if (blockIdx.y == 0) {
        float a0 = bv[t], a1 = 0.f;
#pragma unroll 8
        for (int d = 0; d < D; d += 2) {
            a0 += q0[d]     * Wv[d * D + t];
            a1 += q0[d + 1] * Wv[(d + 1) * D + t];
        }
        float r = a0 + a1;
        g_VQ[q * D + t] = r;
        r0v = r * Wf[t];
    } else {
        const float4* wr = reinterpret_cast<const float4*>(Wk + (size_t)t * D);
        float a0 = 0.f, a1 = 0.f;
#pragma unroll 8
        for (int i = 0; i < D / 8; i++) {
            float4 w0 = wr[2 * i], w1 = wr[2 * i + 1];
            a0 += w0.x * q0[8*i+0] + w0.y * q0[8*i+1] + w0.z * q0[8*i+2] + w0.w * q0[8*i+3];
            a1 += w1.x * q0[8*i+4] + w1.y * q0[8*i+5] + w1.z * q0[8*i+6] + w1.w * q0[8*i+7];
        }
        float r = a0 + a1;
        g_Ak[q * D + t] = r;
        r0v = q0[t] * r;
        r1v = q0[t] * bk[t];
    }
#pragma unroll
    for (int o = 16; o; o >>= 1) {
        r0v += __shfl_xor_sync(0xffffffffu, r0v, o);
        r1v += __shfl_xor_sync(0xffffffffu, r1v, o);
    }
    if (lane == 0) { red[0][w] = r0v; red[1][w] = r1v; }
    __syncthreads();
    if (w == 0) {
        float x0 = (lane < 16) ? red[0][lane] : 0.f;
        float x1 = (lane < 16) ? red[1][lane] : 0.f;
#pragma unroll
        for (int o = 8; o; o >>= 1) {
            x0 += __shfl_xor_sync(0xffffffffu, x0, o);
            x1 += __shfl_xor_sync(0xffffffffu, x1, o);
        }
        if (lane == 0) {
            if (blockIdx.y == 0) {
                g_tq[q] = x0;
            } else {
                g_qbk[q] = x1;
                g_sself[q] = (x0 + x1) * SCALE;
            }
        }
    }
}

// ---------------------------------------------------------------------------
// k_sp: fused. Blocks 0..255 (512 thr): sp scores for 16 token rows AND the
// bf16 hi/lo split of those patch rows. Blocks 256..319: Wv transpose/split.
// ---------------------------------------------------------------------------
__global__ __launch_bounds__(512) void k_sp(const float* __restrict__ patch,
                                            const float* __restrict__ Wv) {
    __shared__ float Aks[QN * D];
    __shared__ float qb[QN];
    __shared__ float tile[64][65];
    int t = threadIdx.x;
    if (blockIdx.x < 256) {
        float4* As4 = reinterpret_cast<float4*>(Aks);
        const float4* g4 = reinterpret_cast<const float4*>(g_Ak);
#pragma unroll
        for (int i = 0; i < 4; i++) As4[t + i * 512] = g4[t + i * 512];
        if (t < QN) qb[t] = g_qbk[t];
        __syncthreads();

        int w = t >> 5, lane = t & 31;
        int row = blockIdx.x * 16 + w;
        const float* pr = patch + (size_t)row * D;
        float acc[QN];
#pragma unroll
        for (int q = 0; q < QN; q++) acc[q] = 0.f;
#pragma unroll
        for (int c = 0; c < D / 32; c++) {
            int col = lane + c * 32;
            float pv = pr[col];
            __nv_bfloat16 h = __float2bfloat16_rn(pv);
            g_Ahi[(size_t)row * D + col] = h;
            g_Alo[(size_t)row * D + col] = __float2bfloat16_rn(pv - __bfloat162float(h));
#pragma unroll
            for (int q = 0; q < QN; q++) acc[q] += pv * Aks[q * D + col];
        }
#pragma unroll
        for (int q = 0; q < QN; q++) {
            float v = acc[q];
#pragma unroll
            for (int o = 16; o; o >>= 1) v += __shfl_xor_sync(0xffffffffu, v, o);
            if (lane == 0) g_sp[row * QN + q] = (v + qb[q]) * SCALE;
        }
    } else {
        int b = blockIdx.x - 256;
        int c0 = (b & 7) * 64, r0 = (b >> 3) * 64;
        int j = t & 63, i0 = t >> 6;
#pragma unroll
        for (int k = 0; k < 8; k++) {
            int i = i0 + k * 8;
            tile[i][j] = Wv[(size_t)(r0 + i) * D + c0 + j];
        }
        __syncthreads();
#pragma unroll
        for (int k = 0; k < 8; k++) {
            int i = i0 + k * 8;
            float v = tile[j][i];
            size_t o = (size_t)(c0 + i) * D + r0 + j;
            __nv_bfloat16 h = __float2bfloat16_rn(v);
            g_Bhi[o] = h;
            g_Blo[o] = __float2bfloat16_rn(v - __bfloat162float(h));
        }
    }
}

// ---------------------------------------------------------------------------
// k_gemm_mma: Vp = patch @ Wv + bv via mma.sync bf16 (2-term split, 3 products)
// CTA tile 128x64, 256 threads, 3-stage cp.async, 2 CTAs/SM.
// ---------------------------------------------------------------------------
#define A_BYTES  10240
#define B_BYTES  5120
#define OFF_ALO  10240
#define OFF_BHI  20480
#define OFF_BLO  25600
#define STAGE_B  30720
#define SMEM_MMA (3 * STAGE_B)

__global__ __launch_bounds__(256, 2) void k_gemm_mma(const float* __restrict__ bv,
                                                     const float* __restrict__ Wf) {
    extern __shared__ char sm[];
    uint32_t sbase = smem_u32(sm);
    int t = threadIdx.x, wid = t >> 5, lane = t & 31;
    int m0 = blockIdx.y * 128, n0 = blockIdx.x * 64;
    int wm = wid >> 1, wn = wid & 1;

    float acc[2][4][4];
#pragma unroll
    for (int i = 0; i < 2; i++)
#pragma unroll
        for (int j = 0; j < 4; j++)
#pragma unroll
            for (int k = 0; k < 4; k++) acc[i][j][k] = 0.f;

    int rowA[2], segA[2];
#pragma unroll
    for (int h = 0; h < 2; h++) {
        int rem = h * 256 + t;
        rowA[h] = rem >> 2; segA[h] = rem & 3;
    }
    int rowB = t >> 2, segB = t & 3;

    auto load_chunk = [&](int c) {
        int s = c % 3, k0 = c * 32;
        uint32_t base = sbase + s * STAGE_B;
#pragma unroll
        for (int h = 0; h < 2; h++) {
            int r = rowA[h], seg = segA[h];
            size_t go = (size_t)(m0 + r) * D + k0 + seg * 8;
            uint32_t so = (uint32_t)(r * 80 + seg * 16);
            cp16(base + so, g_Ahi + go);
            cp16(base + OFF_ALO + so, g_Alo + go);
        }
        {
            size_t go = (size_t)(n0 + rowB) * D + k0 + segB * 8;
            uint32_t so = (uint32_t)(rowB * 80 + segB * 16);
            cp16(base + OFF_BHI + so, g_Bhi + go);
            cp16(base + OFF_BLO + so, g_Blo + go);
        }
        CP_COMMIT();
    };

    uint32_t aoff = (uint32_t)((wm * 32 + (lane & 15)) * 80 + (lane >> 4) * 16);
    uint32_t boff = (uint32_t)((wn * 32 + (lane & 7) + ((lane >> 4) & 1) * 8) * 80
                               + ((lane >> 3) & 1) * 16);

    load_chunk(0);
    load_chunk(1);
    for (int c = 0; c < 16; c++) {
        if (c <= 13) { load_chunk(c + 2); CP_WAIT(2); }
        else if (c == 14) { CP_WAIT(1); }
        else { CP_WAIT(0); }
        __syncthreads();
        uint32_t st = sbase + (c % 3) * STAGE_B;
#pragma unroll
        for (int ks = 0; ks < 2; ks++) {
            uint32_t ah[2][4], al[2][4], bh[2][4], bl[2][4];
#pragma unroll
            for (int mt = 0; mt < 2; mt++) {
                ldm_x4(ah[mt], st + aoff + mt * (16 * 80) + ks * 32);
                ldm_x4(al[mt], st + OFF_ALO + aoff + mt * (16 * 80) + ks * 32);
            }
#pragma unroll
            for (int np = 0; np < 2; np++) {
                ldm_x4(bh[np], st + OFF_BHI + boff + np * (16 * 80) + ks * 32);
                ldm_x4(bl[np], st + OFF_BLO + boff + np * (16 * 80) + ks * 32);
            }
#pragma unroll
            for (int mt = 0; mt < 2; mt++)
#pragma unroll
                for (int np = 0; np < 2; np++) {
                    mma16816(acc[mt][2 * np],     ah[mt], &bh[np][0]);
                    mma16816(acc[mt][2 * np + 1], ah[mt], &bh[np][2]);
                    mma16816(acc[mt][2 * np],     ah[mt], &bl[np][0]);
                    mma16816(acc[mt][2 * np + 1], ah[mt], &bl[np][2]);
                    mma16816(acc[mt][2 * np],     al[mt], &bh[np][0]);
                    mma16816(acc[mt][2 * np + 1], al[mt], &bh[np][2]);
                }
        }
        __syncthreads();
    }

    int g = lane >> 2, tig = lane & 3;
    float bcol0[4], bcol1[4], wcol0[4], wcol1[4];
#pragma unroll
    for (int nt = 0; nt < 4; nt++) {
        int col = n0 + wn * 32 + nt * 8 + tig * 2;
        bcol0[nt] = __ldg(bv + col); bcol1[nt] = __ldg(bv + col + 1);
        wcol0[nt] = __ldg(Wf + col); wcol1[nt] = __ldg(Wf + col + 1);
    }
    float* spf = reinterpret_cast<float*>(sm);
#pragma unroll
    for (int mt = 0; mt < 2; mt++) {
        int lr = wm * 32 + mt * 16 + g;
        int r = m0 + lr;
        float pf0 = 0.f, pf1 = 0.f;
#pragma unroll
        for (int nt = 0; nt < 4; nt++) {
            int col = n0 + wn * 32 + nt * 8 + tig * 2;
            float2 v0 = make_float2(acc[mt][nt][0] + bcol0[nt], acc[mt][nt][1] + bcol1[nt]);
            float2 v1 = make_float2(acc[mt][nt][2] + bcol0[nt], acc[mt][nt][3] + bcol1[nt]);
            *reinterpret_cast<float2*>(&g_Vp[(size_t)r * D + col]) = v0;
            *reinterpret_cast<float2*>(&g_Vp[(size_t)(r + 8) * D + col]) = v1;
            pf0 += v0.x * wcol0[nt] + v0.y * wcol1[nt];
            pf1 += v1.x * wcol0[nt] + v1.y * wcol1[nt];
        }
        pf0 += __shfl_xor_sync(0xffffffffu, pf0, 1);
        pf0 += __shfl_xor_sync(0xffffffffu, pf0, 2);
        pf1 += __shfl_xor_sync(0xffffffffu, pf1, 1);
        pf1 += __shfl_xor_sync(0xffffffffu, pf1, 2);
        if (tig == 0) {
            spf[wn * 128 + lr] = pf0;
            spf[wn * 128 + lr + 8] = pf1;
        }
    }
    __syncthreads();
    if (t < 128) {
        g_pfp[blockIdx.x][m0 + t] = spf[t] + spf[128 + t];
    }
}

// ---------------------------------------------------------------------------
// k_combine: one block per group n, 256 threads. Collapsed form:
//  out[d] = sum_q c0[q]*VQ[q,d] + sum_p e[p]*Vp[idx_p,d]
// Gather loop split across two thread-halves (p 0..31 / 32..63) for 2x
// occupancy and half the per-thread dependent-gather chain.
// ---------------------------------------------------------------------------
__global__ __launch_bounds__(256) void k_combine(const int* __restrict__ indices,
                                                 const unsigned* __restrict__ mask,
                                                 const float* __restrict__ bf,
                                                 float* __restrict__ out) {
    __shared__ float S[QN][72];       // col 0 = self, 1..64 = p (unnorm exp)
    __shared__ int sidx[PP];
    __shared__ unsigned smk[PP];
    __shared__ float pfs[PP];
    __shared__ float tqs[QN];
    __shared__ float invq[QN];
    __shared__ float fq[QN];
    __shared__ float es[PP];
    __shared__ __align__(16) float4 part[128];
    int n = blockIdx.x, t = threadIdx.x;
    int lane = t & 31, w = t >> 5;
    const float NINF = __int_as_float(0xff800000u);

    if (t < PP) {
        sidx[t] = indices[n * PP + t];
        smk[t]  = mask[n * PP + t];
    }
    if (t < QN) tqs[t] = g_tq[t];
    __syncthreads();

    // Phase A: all 256 threads: p = t&63, q-quarter = t>>6 (4 q each)
    {
        int p = t & 63, qq = t >> 6;
        int idx = sidx[p];
        float4 v;
        if (smk[p] != 0u) {
            v = reinterpret_cast<const float4*>(g_sp + (size_t)idx * QN)[qq];
        } else {
            v = make_float4(NINF, NINF, NINF, NINF);
        }
        int q0 = qq * 4;
        S[q0 + 0][p + 1] = v.x; S[q0 + 1][p + 1] = v.y;
        S[q0 + 2][p + 1] = v.z; S[q0 + 3][p + 1] = v.w;
        if (t < PP) {
            int idx2 = sidx[t];
            float s = 0.f;
#pragma unroll
            for (int b = 0; b < 8; b++) s += g_pfp[b][idx2];
            pfs[t] = s;
        }
    }
    if (t < QN) S[t][0] = g_sself[t];
    __syncthreads();

    // Phase B: softmax per q; 8 warps x 2 q each
    {
        float bf0 = bf[0];
#pragma unroll
        for (int qi = 0; qi < 2; qi++) {
            int q = w * 2 + qi;
            float v0 = S[q][lane], v1 = S[q][lane + 32];
            float v2 = (lane == 0) ? S[q][64] : NINF;
            float mx = fmaxf(fmaxf(v0, v1), v2);
#pragma unroll
            for (int o = 16; o; o >>= 1) mx = fmaxf(mx, __shfl_xor_sync(0xffffffffu, mx, o));
            float e0 = expf(v0 - mx), e1 = expf(v1 - mx);
            float e2 = (lane == 0) ? expf(v2 - mx) : 0.f;
            float s = e0 + e1 + e2;
#pragma unroll
            for (int o = 16; o; o >>= 1) s += __shfl_xor_sync(0xffffffffu, s, o);
            S[q][lane] = e0; S[q][lane + 32] = e1;
            if (lane == 0) S[q][64] = e2;
            float pr0 = (lane == 0) ? tqs[q] : pfs[lane - 1];
            float fp = e0 * pr0 + e1 * pfs[lane + 31];
            if (lane == 0) fp += e2 * pfs[63];
#pragma unroll
            for (int o = 16; o; o >>= 1) fp += __shfl_xor_sync(0xffffffffu, fp, o);
            if (lane == 0) {
                invq[q] = 1.f / s;
                fq[q] = fp / s + bf0;
            }
        }
    }
    __syncthreads();

    // Phase C: fusion softmax over q (redundant per thread)
    float c[QN];
    {
        float fv[QN], mx = -3.4e38f;
#pragma unroll
        for (int q = 0; q < QN; q++) { fv[q] = fq[q]; mx = fmaxf(mx, fv[q]); }
        float s = 0.f;
#pragma unroll
        for (int q = 0; q < QN; q++) { fv[q] = expf(fv[q] - mx); s += fv[q]; }
        float inv = 1.f / s;
#pragma unroll
        for (int q = 0; q < QN; q++) c[q] = fv[q] * inv * invq[q];
    }

    // Phase D: effective per-row weights
    if (t < PP) {
        float ep = 0.f;
#pragma unroll
        for (int q = 0; q < QN; q++) ep += c[q] * S[q][t + 1];
        es[t] = ep;
    }
    __syncthreads();

    // Phase E: split gather. half 0: VQ term + p 0..31; half 1: p 32..63.
    int tl = t & 127, half = t >> 7;
    float4 o = make_float4(0.f, 0.f, 0.f, 0.f);
    if (half == 0) {
        const float4* VQ4 = reinterpret_cast<const float4*>(g_VQ);
#pragma unroll
        for (int q = 0; q < QN; q++) {
            float c0 = c[q] * S[q][0];
            float4 vq = VQ4[q * 128 + tl];
            o.x += c0 * vq.x; o.y += c0 * vq.y;
            o.z += c0 * vq.z; o.w += c0 * vq.w;
        }
    }
    const float4* Vp4 = reinterpret_cast<const float4*>(g_Vp);
#pragma unroll 8
    for (int pi = 0; pi < 32; pi++) {
        int p = half * 32 + pi;
        float ep = es[p];
        if (ep != 0.f) {
            float4 v = Vp4[(size_t)sidx[p] * 128 + tl];
            o.x += ep * v.x; o.y += ep * v.y;
            o.z += ep * v.z; o.w += ep * v.w;
        }
    }
    if (half == 1) part[tl] = o;
    __syncthreads();
    if (half == 0) {
        float4 p1 = part[tl];
        o.x += p1.x; o.y += p1.y; o.z += p1.z; o.w += p1.w;
        reinterpret_cast<float4*>(out)[(size_t)n * 128 + tl] = o;
    }
}

// ---------------------------------------------------------------------------
extern "C" void kernel_launch(void* const* d_in, const int* in_sizes, int n_in,
                              void* d_out, int out_size) {
    (void)in_sizes; (void)n_in; (void)out_size;
    const float* patch   = (const float*)d_in[0];
    const float* query   = (const float*)d_in[1];
    const float* Wk      = (const float*)d_in[2];
    const float* bk      = (const float*)d_in[3];
    const float* Wv      = (const float*)d_in[4];
    const float* bv      = (const float*)d_in[5];
    const float* Wf      = (const float*)d_in[6];
    const float* bf      = (const float*)d_in[7];
    const int* indices   = (const int*)d_in[8];
    const unsigned* mask = (const unsigned*)d_in[9];
    float* out           = (float*)d_out;

    cudaFuncSetAttribute(k_gemm_mma, cudaFuncAttributeMaxDynamicSharedMemorySize, SMEM_MMA);

    k_pre<<<dim3(QN, 2), D>>>(query, Wk, Wv, bv, bk, Wf);
    k_sp<<<256 + 64, 512>>>(patch, Wv);
    k_gemm_mma<<<dim3(8, 32), 256, SMEM_MMA>>>(bv, Wf);
    k_combine<<<NG, 256>>>(indices, mask, bf, out);
}

// round 12
// speedup vs baseline: 1.5518x; 1.5518x over previous
#include <cuda_runtime.h>
#include <cuda_bf16.h>
#include <math.h>
#include <stdint.h>

// Problem constants
#define D   512
#define QN  16
#define NT  4096   // B*L tokens
#define NG  512    // N gathered groups
#define PP  64     // group size P

#define SCALE 0.04419417382415922f  // 1/sqrt(512)

// Scratch (allocation-free: __device__ globals)
__device__ float g_Vp[NT * D];            // patch @ Wv + bv      [4096,512]
__device__ __nv_bfloat16 g_Ahi[NT * D];   // bf16 hi split of patch
__device__ __nv_bfloat16 g_Alo[NT * D];   // bf16 lo split of patch
__device__ __nv_bfloat16 g_Bhi[D * D];    // bf16 hi split of Wv^T ([n][k])
__device__ __nv_bfloat16 g_Blo[D * D];    // bf16 lo split of Wv^T
__device__ float g_sp[NT * QN];           // scaled patch scores  [4096,16]
__device__ float g_VQ[QN * D];            // Q0 @ Wv + bv         [16,512]
__device__ float g_Ak[QN * D];            // (Wk @ Q0^T)^T        [16,512]
__device__ float g_pfp[8][NT];            // partial Vp @ Wf per n-tile
__device__ float g_tq[QN];                // VQ @ Wf              [16]
__device__ float g_sself[QN];             // self-token scores    [16]
__device__ float g_qbk[QN];               // Q0[q] . bk           [16]

// ---- PTX helpers (all sm_80-level, valid for compute_103 target) -----------
__device__ __forceinline__ uint32_t smem_u32(const void* p) {
    uint32_t a;
    asm("{ .reg .u64 tmp; cvta.to.shared.u64 tmp, %1; cvt.u32.u64 %0, tmp; }"
        : "=r"(a) : "l"(p));
    return a;
}
__device__ __forceinline__ void cp16(uint32_t sdst, const void* gsrc) {
    asm volatile("cp.async.cg.shared.global [%0], [%1], 16;"
                 :: "r"(sdst), "l"(gsrc) : "memory");
}
#define CP_COMMIT() asm volatile("cp.async.commit_group;" ::: "memory")
#define CP_WAIT(n)  asm volatile("cp.async.wait_group %0;" :: "n"(n) : "memory")

__device__ __forceinline__ void ldm_x4(uint32_t* r, uint32_t addr) {
    asm volatile("ldmatrix.sync.aligned.m8n8.x4.shared.b16 {%0,%1,%2,%3}, [%4];"
                 : "=r"(r[0]), "=r"(r[1]), "=r"(r[2]), "=r"(r[3]) : "r"(addr));
}
__device__ __forceinline__ void mma16816(float* c, const uint32_t* a, const uint32_t* b) {
    asm volatile("mma.sync.aligned.m16n8k16.row.col.f32.bf16.bf16.f32 "
                 "{%0,%1,%2,%3}, {%4,%5,%6,%7}, {%8,%9}, {%0,%1,%2,%3};"
                 : "+f"(c[0]), "+f"(c[1]), "+f"(c[2]), "+f"(c[3])
                 : "r"(a[0]), "r"(a[1]), "r"(a[2]), "r"(a[3]), "r"(b[0]), "r"(b[1]));
}

// ---------------------------------------------------------------------------
// k_pre: grid (16, 2), block 512. Fused projections + scalar reductions.
// ---------------------------------------------------------------------------
__global__ void k_pre(const float* __restrict__ query, const float* __restrict__ Wk,
                      const float* __restrict__ Wv, const float* __restrict__ bv,
                      const float* __restrict__ bk, const float* __restrict__ Wf) {
    __shared__ float q0[D];
    __shared__ float red[2][16];
    int q = blockIdx.x, t = threadIdx.x;
    int w = t >> 5, lane = t & 31;
    q0[t] = query[q * D + t];
    __syncthreads();

    float r0v = 0.f, r1v = 0.f;
    if (blockIdx.y == 0) {
        float a0 = bv[t], a1 = 0.f;
#pragma unroll 8
        for (int d = 0; d < D; d += 2) {
            a0 += q0[d]     * Wv[d * D + t];
            a1 += q0[d + 1] * Wv[(d + 1) * D + t];
        }
        float r = a0 + a1;
        g_VQ[q * D + t] = r;
        r0v = r * Wf[t];
    } else {
        const float4* wr = reinterpret_cast<const float4*>(Wk + (size_t)t * D);
        float a0 = 0.f, a1 = 0.f;
#pragma unroll 8
        for (int i = 0; i < D / 8; i++) {
            float4 w0 = wr[2 * i], w1 = wr[2 * i + 1];
            a0 += w0.x * q0[8*i+0] + w0.y * q0[8*i+1] + w0.z * q0[8*i+2] + w0.w * q0[8*i+3];
            a1 += w1.x * q0[8*i+4] + w1.y * q0[8*i+5] + w1.z * q0[8*i+6] + w1.w * q0[8*i+7];
        }
        float r = a0 + a1;
        g_Ak[q * D + t] = r;
        r0v = q0[t] * r;
        r1v = q0[t] * bk[t];
    }
#pragma unroll
    for (int o = 16; o; o >>= 1) {
        r0v += __shfl_xor_sync(0xffffffffu, r0v, o);
        r1v += __shfl_xor_sync(0xffffffffu, r1v, o);
    }
    if (lane == 0) { red[0][w] = r0v; red[1][w] = r1v; }
    __syncthreads();
    if (w == 0) {
        float x0 = (lane < 16) ? red[0][lane] : 0.f;
        float x1 = (lane < 16) ? red[1][lane] : 0.f;
#pragma unroll
        for (int o = 8; o; o >>= 1) {
            x0 += __shfl_xor_sync(0xffffffffu, x0, o);
            x1 += __shfl_xor_sync(0xffffffffu, x1, o);
        }
        if (lane == 0) {
            if (blockIdx.y == 0) {
                g_tq[q] = x0;
            } else {
                g_qbk[q] = x1;
                g_sself[q] = (x0 + x1) * SCALE;
            }
        }
    }
}

// ---------------------------------------------------------------------------
// k_sp: fused. Blocks 0..255 (512 thr): sp scores for 16 token rows AND the
// bf16 hi/lo split of those patch rows. Blocks 256..319: Wv transpose/split.
// ---------------------------------------------------------------------------
__global__ __launch_bounds__(512) void k_sp(const float* __restrict__ patch,
                                            const float* __restrict__ Wv) {
    __shared__ float Aks[QN * D];
    __shared__ float qb[QN];
    __shared__ float tile[64][65];
    int t = threadIdx.x;
    if (blockIdx.x < 256) {
        float4* As4 = reinterpret_cast<float4*>(Aks);
        const float4* g4 = reinterpret_cast<const float4*>(g_Ak);
#pragma unroll
        for (int i = 0; i < 4; i++) As4[t + i * 512] = g4[t + i * 512];
        if (t < QN) qb[t] = g_qbk[t];
        __syncthreads();

        int w = t >> 5, lane = t & 31;
        int row = blockIdx.x * 16 + w;
        const float* pr = patch + (size_t)row * D;
        float acc[QN];
#pragma unroll
        for (int q = 0; q < QN; q++) acc[q] = 0.f;
#pragma unroll
        for (int c = 0; c < D / 32; c++) {
            int col = lane + c * 32;
            float pv = pr[col];
            __nv_bfloat16 h = __float2bfloat16_rn(pv);
            g_Ahi[(size_t)row * D + col] = h;
            g_Alo[(size_t)row * D + col] = __float2bfloat16_rn(pv - __bfloat162float(h));
#pragma unroll
            for (int q = 0; q < QN; q++) acc[q] += pv * Aks[q * D + col];
        }
#pragma unroll
        for (int q = 0; q < QN; q++) {
            float v = acc[q];
#pragma unroll
            for (int o = 16; o; o >>= 1) v += __shfl_xor_sync(0xffffffffu, v, o);
            if (lane == 0) g_sp[row * QN + q] = (v + qb[q]) * SCALE;
        }
    } else {
        int b = blockIdx.x - 256;
        int c0 = (b & 7) * 64, r0 = (b >> 3) * 64;
        int j = t & 63, i0 = t >> 6;
#pragma unroll
        for (int k = 0; k < 8; k++) {
            int i = i0 + k * 8;
            tile[i][j] = Wv[(size_t)(r0 + i) * D + c0 + j];
        }
        __syncthreads();
#pragma unroll
        for (int k = 0; k < 8; k++) {
            int i = i0 + k * 8;
            float v = tile[j][i];
            size_t o = (size_t)(c0 + i) * D + r0 + j;
            __nv_bfloat16 h = __float2bfloat16_rn(v);
            g_Bhi[o] = h;
            g_Blo[o] = __float2bfloat16_rn(v - __bfloat162float(h));
        }
    }
}

// ---------------------------------------------------------------------------
// k_gemm_mma: Vp = patch @ Wv + bv via mma.sync bf16 (2-term split, 3 products)
// CTA tile 128x64, 256 threads, 3-stage cp.async, 2 CTAs/SM.
// ---------------------------------------------------------------------------
#define A_BYTES  10240
#define B_BYTES  5120
#define OFF_ALO  10240
#define OFF_BHI  20480
#define OFF_BLO  25600
#define STAGE_B  30720
#define SMEM_MMA (3 * STAGE_B)

__global__ __launch_bounds__(256, 2) void k_gemm_mma(const float* __restrict__ bv,
                                                     const float* __restrict__ Wf) {
    extern __shared__ char sm[];
    uint32_t sbase = smem_u32(sm);
    int t = threadIdx.x, wid = t >> 5, lane = t & 31;
    int m0 = blockIdx.y * 128, n0 = blockIdx.x * 64;
    int wm = wid >> 1, wn = wid & 1;

    float acc[2][4][4];
#pragma unroll
    for (int i = 0; i < 2; i++)
#pragma unroll
        for (int j = 0; j < 4; j++)
#pragma unroll
            for (int k = 0; k < 4; k++) acc[i][j][k] = 0.f;

    int rowA[2], segA[2];
#pragma unroll
    for (int h = 0; h < 2; h++) {
        int rem = h * 256 + t;
        rowA[h] = rem >> 2; segA[h] = rem & 3;
    }
    int rowB = t >> 2, segB = t & 3;

    auto load_chunk = [&](int c) {
        int s = c % 3, k0 = c * 32;
        uint32_t base = sbase + s * STAGE_B;
#pragma unroll
        for (int h = 0; h < 2; h++) {
            int r = rowA[h], seg = segA[h];
            size_t go = (size_t)(m0 + r) * D + k0 + seg * 8;
            uint32_t so = (uint32_t)(r * 80 + seg * 16);
            cp16(base + so, g_Ahi + go);
            cp16(base + OFF_ALO + so, g_Alo + go);
        }
        {
            size_t go = (size_t)(n0 + rowB) * D + k0 + segB * 8;
            uint32_t so = (uint32_t)(rowB * 80 + segB * 16);
            cp16(base + OFF_BHI + so, g_Bhi + go);
            cp16(base + OFF_BLO + so, g_Blo + go);
        }
        CP_COMMIT();
    };

    uint32_t aoff = (uint32_t)((wm * 32 + (lane & 15)) * 80 + (lane >> 4) * 16);
    uint32_t boff = (uint32_t)((wn * 32 + (lane & 7) + ((lane >> 4) & 1) * 8) * 80
                               + ((lane >> 3) & 1) * 16);

    load_chunk(0);
    load_chunk(1);
    for (int c = 0; c < 16; c++) {
        if (c <= 13) { load_chunk(c + 2); CP_WAIT(2); }
        else if (c == 14) { CP_WAIT(1); }
        else { CP_WAIT(0); }
        __syncthreads();
        uint32_t st = sbase + (c % 3) * STAGE_B;
#pragma unroll
        for (int ks = 0; ks < 2; ks++) {
            uint32_t ah[2][4], al[2][4], bh[2][4], bl[2][4];
#pragma unroll
            for (int mt = 0; mt < 2; mt++) {
                ldm_x4(ah[mt], st + aoff + mt * (16 * 80) + ks * 32);
                ldm_x4(al[mt], st + OFF_ALO + aoff + mt * (16 * 80) + ks * 32);
            }
#pragma unroll
            for (int np = 0; np < 2; np++) {
                ldm_x4(bh[np], st + OFF_BHI + boff + np * (16 * 80) + ks * 32);
                ldm_x4(bl[np], st + OFF_BLO + boff + np * (16 * 80) + ks * 32);
            }
#pragma unroll
            for (int mt = 0; mt < 2; mt++)
#pragma unroll
                for (int np = 0; np < 2; np++) {
                    mma16816(acc[mt][2 * np],     ah[mt], &bh[np][0]);
                    mma16816(acc[mt][2 * np + 1], ah[mt], &bh[np][2]);
                    mma16816(acc[mt][2 * np],     ah[mt], &bl[np][0]);
                    mma16816(acc[mt][2 * np + 1], ah[mt], &bl[np][2]);
                    mma16816(acc[mt][2 * np],     al[mt], &bh[np][0]);
                    mma16816(acc[mt][2 * np + 1], al[mt], &bh[np][2]);
                }
        }
        __syncthreads();
    }

    int g = lane >> 2, tig = lane & 3;
    float bcol0[4], bcol1[4], wcol0[4], wcol1[4];
#pragma unroll
    for (int nt = 0; nt < 4; nt++) {
        int col = n0 + wn * 32 + nt * 8 + tig * 2;
        bcol0[nt] = __ldg(bv + col); bcol1[nt] = __ldg(bv + col + 1);
        wcol0[nt] = __ldg(Wf + col); wcol1[nt] = __ldg(Wf + col + 1);
    }
    float* spf = reinterpret_cast<float*>(sm);
#pragma unroll
    for (int mt = 0; mt < 2; mt++) {
        int lr = wm * 32 + mt * 16 + g;
        int r = m0 + lr;
        float pf0 = 0.f, pf1 = 0.f;
#pragma unroll
        for (int nt = 0; nt < 4; nt++) {
            int col = n0 + wn * 32 + nt * 8 + tig * 2;
            float2 v0 = make_float2(acc[mt][nt][0] + bcol0[nt], acc[mt][nt][1] + bcol1[nt]);
            float2 v1 = make_float2(acc[mt][nt][2] + bcol0[nt], acc[mt][nt][3] + bcol1[nt]);
            *reinterpret_cast<float2*>(&g_Vp[(size_t)r * D + col]) = v0;
            *reinterpret_cast<float2*>(&g_Vp[(size_t)(r + 8) * D + col]) = v1;
            pf0 += v0.x * wcol0[nt] + v0.y * wcol1[nt];
            pf1 += v1.x * wcol0[nt] + v1.y * wcol1[nt];
        }
        pf0 += __shfl_xor_sync(0xffffffffu, pf0, 1);
        pf0 += __shfl_xor_sync(0xffffffffu, pf0, 2);
        pf1 += __shfl_xor_sync(0xffffffffu, pf1, 1);
        pf1 += __shfl_xor_sync(0xffffffffu, pf1, 2);
        if (tig == 0) {
            spf[wn * 128 + lr] = pf0;
            spf[wn * 128 + lr + 8] = pf1;
        }
    }
    __syncthreads();
    if (t < 128) {
        g_pfp[blockIdx.x][m0 + t] = spf[t] + spf[128 + t];
    }
}

// ---------------------------------------------------------------------------
// k_combine: one block per group n, 128 threads. Collapsed form:
//  out[d] = sum_q c0[q]*VQ[q,d] + sum_p e[p]*Vp[idx_p,d]
// Gather loop is UNCONDITIONAL (masked rows have e[p]==0 exactly) so the 64
// LDG.128 gathers are independent and batched by the scheduler (high MLP).
// ---------------------------------------------------------------------------
__global__ __launch_bounds__(128) void k_combine(const int* __restrict__ indices,
                                                 const unsigned* __restrict__ mask,
                                                 const float* __restrict__ bf,
                                                 float* __restrict__ out) {
    __shared__ float S[QN][72];       // col 0 = self, 1..64 = p (unnorm exp)
    __shared__ int sidx[PP];
    __shared__ unsigned smk[PP];
    __shared__ float pfs[PP];
    __shared__ float tqs[QN];
    __shared__ float invq[QN];
    __shared__ float fq[QN];
    __shared__ float es[PP];
    int n = blockIdx.x, t = threadIdx.x;
    int lane = t & 31, w = t >> 5;
    const float NINF = __int_as_float(0xff800000u);

    if (t < PP) {
        sidx[t] = indices[n * PP + t];
        smk[t]  = mask[n * PP + t];
    }
    if (t < QN) tqs[t] = g_tq[t];
    __syncthreads();

    // Phase A: gather scores + pf partial sums
    {
        int p = t & 63, half = t >> 6;
        int idx = sidx[p];
        float4 v0, v1;
        if (smk[p] != 0u) {
            const float4* sp4 = reinterpret_cast<const float4*>(g_sp + (size_t)idx * QN + half * 8);
            v0 = sp4[0]; v1 = sp4[1];
        } else {
            v0 = make_float4(NINF, NINF, NINF, NINF);
            v1 = v0;
        }
        int q0 = half * 8;
        S[q0 + 0][p + 1] = v0.x; S[q0 + 1][p + 1] = v0.y;
        S[q0 + 2][p + 1] = v0.z; S[q0 + 3][p + 1] = v0.w;
        S[q0 + 4][p + 1] = v1.x; S[q0 + 5][p + 1] = v1.y;
        S[q0 + 6][p + 1] = v1.z; S[q0 + 7][p + 1] = v1.w;
        if (t < PP) {
            int idx2 = sidx[t];
            float s = 0.f;
#pragma unroll
            for (int b = 0; b < 8; b++) s += g_pfp[b][idx2];
            pfs[t] = s;
        }
    }
    if (t < QN) S[t][0] = g_sself[t];
    __syncthreads();

    // Phase B: per-q softmax (unnorm exp kept) + fused f[q] projection
    {
        float bf0 = bf[0];
#pragma unroll
        for (int qi = 0; qi < 4; qi++) {
            int q = w * 4 + qi;
            float v0 = S[q][lane], v1 = S[q][lane + 32];
            float v2 = (lane == 0) ? S[q][64] : NINF;
            float mx = fmaxf(fmaxf(v0, v1), v2);
#pragma unroll
            for (int o = 16; o; o >>= 1) mx = fmaxf(mx, __shfl_xor_sync(0xffffffffu, mx, o));
            float e0 = expf(v0 - mx), e1 = expf(v1 - mx);
            float e2 = (lane == 0) ? expf(v2 - mx) : 0.f;
            float s = e0 + e1 + e2;
#pragma unroll
            for (int o = 16; o; o >>= 1) s += __shfl_xor_sync(0xffffffffu, s, o);
            S[q][lane] = e0; S[q][lane + 32] = e1;
            if (lane == 0) S[q][64] = e2;
            float pr0 = (lane == 0) ? tqs[q] : pfs[lane - 1];
            float fp = e0 * pr0 + e1 * pfs[lane + 31];
            if (lane == 0) fp += e2 * pfs[63];
#pragma unroll
            for (int o = 16; o; o >>= 1) fp += __shfl_xor_sync(0xffffffffu, fp, o);
            if (lane == 0) {
                invq[q] = 1.f / s;
                fq[q] = fp / s + bf0;
            }
        }
    }
    __syncthreads();

    // Phase C: fusion softmax over q (redundant per thread)
    float c[QN];
    {
        float fv[QN], mx = -3.4e38f;
#pragma unroll
        for (int q = 0; q < QN; q++) { fv[q] = fq[q]; mx = fmaxf(mx, fv[q]); }
        float s = 0.f;
#pragma unroll
        for (int q = 0; q < QN; q++) { fv[q] = expf(fv[q] - mx); s += fv[q]; }
        float inv = 1.f / s;
#pragma unroll
        for (int q = 0; q < QN; q++) c[q] = fv[q] * inv * invq[q];
    }

    // Phase D: effective per-row weights
    if (t < PP) {
        float ep = 0.f;
#pragma unroll
        for (int q = 0; q < QN; q++) ep += c[q] * S[q][t + 1];
        es[t] = ep;
    }
    __syncthreads();

    // Phase E: output accumulation. Unconditional gathers -> high MLP.
    float4 o = make_float4(0.f, 0.f, 0.f, 0.f);
    {
        const float4* VQ4 = reinterpret_cast<const float4*>(g_VQ);
#pragma unroll
        for (int q = 0; q < QN; q++) {
            float c0 = c[q] * S[q][0];
            float4 vq = VQ4[q * 128 + t];
            o.x += c0 * vq.x; o.y += c0 * vq.y;
            o.z += c0 * vq.z; o.w += c0 * vq.w;
        }
    }
    const float4* Vp4 = reinterpret_cast<const float4*>(g_Vp);
#pragma unroll 8
    for (int p = 0; p < PP; p++) {
        float4 v = Vp4[(size_t)sidx[p] * 128 + t];
        float ep = es[p];
        o.x += ep * v.x; o.y += ep * v.y;
        o.z += ep * v.z; o.w += ep * v.w;
    }
    reinterpret_cast<float4*>(out)[(size_t)n * 128 + t] = o;
}

// ---------------------------------------------------------------------------
extern "C" void kernel_launch(void* const* d_in, const int* in_sizes, int n_in,
                              void* d_out, int out_size) {
    (void)in_sizes; (void)n_in; (void)out_size;
    const float* patch   = (const float*)d_in[0];
    const float* query   = (const float*)d_in[1];
    const float* Wk      = (const float*)d_in[2];
    const float* bk      = (const float*)d_in[3];
    const float* Wv      = (const float*)d_in[4];
    const float* bv      = (const float*)d_in[5];
    const float* Wf      = (const float*)d_in[6];
    const float* bf      = (const float*)d_in[7];
    const int* indices   = (const int*)d_in[8];
    const unsigned* mask = (const unsigned*)d_in[9];
    float* out           = (float*)d_out;

    cudaFuncSetAttribute(k_gemm_mma, cudaFuncAttributeMaxDynamicSharedMemorySize, SMEM_MMA);

    k_pre<<<dim3(QN, 2), D>>>(query, Wk, Wv, bv, bk, Wf);
    k_sp<<<256 + 64, 512>>>(patch, Wv);
    k_gemm_mma<<<dim3(8, 32), 256, SMEM_MMA>>>(bv, Wf);
    k_combine<<<NG, 128>>>(indices, mask, bf, out);
}